// round 7
// baseline (speedup 1.0000x reference)
#include <cuda_runtime.h>
#include <math.h>

// Problem dims (fixed by the dataset)
#define LT   512   // sequence length L
#define DIN  512
#define NS   512   // state dim N
#define DOUT 512
#define BZ   32
#define MTOT (BZ*LT)   // 16384 rows for the big GEMMs (m = b*512 + t)

// ---------------- scratch (device globals; no allocation allowed) ------------
__device__ float g_Bq[NS*DIN];
__device__ float g_Cq[DOUT*NS];
__device__ float g_Dq[DOUT*DIN];
__device__ float g_Aq[NS];
__device__ float g_X [BZ*LT*NS];    // X[b,t,n]  = X[m*512 + n]
__device__ float g_DU[BZ*DOUT*LT];  // DU[b,o,t] = DU[(b*512+o)*512 + t]
__device__ float g_S [BZ*LT*NS];    // S[b,t,n]  = S[m*512 + n]

// ---------------- quantizer: matches reference to_float8(4,3) ----------------
// e = clip(floor(log2(|x|+1e-8)), -7, 7); p = 2^e;
// mant = round((|x|/p - 1)*8)/8; out = sign(x)*(1+mant)*p
__device__ __forceinline__ float q8(float x) {
    float xa = fabsf(x);
    float z  = xa + 1e-8f;                       // always normal (>= 1e-8)
    int   e  = (__float_as_int(z) >> 23) - 127;  // floor(log2 z), exact for normals
    e = max(-7, min(7, e));
    float p    = __int_as_float((e + 127) << 23);
    float pinv = __int_as_float((127 - e) << 23);
    // xa*pinv is exact (power-of-2 scale) -> fma matches ref's (xa/p - 1)
    float mant = rintf(fmaf(xa, pinv, -1.0f) * 8.0f) * 0.125f;  // rint = RNE = jnp.round
    float r = (1.0f + mant) * p;
    return copysignf(r, x);                      // x==0 -> r==0 -> +0
}

// ---------------- weight quantization ----------------------------------------
__global__ void quant_weights(const float* __restrict__ A, const float* __restrict__ B,
                              const float* __restrict__ C, const float* __restrict__ D) {
    int i = blockIdx.x * blockDim.x + threadIdx.x;
    if (i < NS*DIN) {
        g_Bq[i] = q8(B[i]);
        g_Cq[i] = q8(C[i]);
        g_Dq[i] = q8(D[i]);
    }
    if (i < NS) g_Aq[i] = q8(A[i]);
}

// ---------------- templated GEMM ---------------------------------------------
// out[m,n] = sum_k A(m,k) * W[n,k]   (W row-major [n][k], 512 cols)
// Accumulation: pure ascending-k fma chain per output element (matches the
// reference contraction's per-element association as closely as possible).
// MODE_X : A = u (u[b,d,t] layout, k strided), W=Bq, out X[m*512+n]           (lanes fast over n)
// MODE_DU: A = u,                              W=Dq, out DU[(b*512+o)*512+t]  (lanes fast over t)
// MODE_Y : A = S (row-major),                  W=Cq, out Y = q8(acc+DU)       (lanes fast over t)
#define MODE_X  0
#define MODE_DU 1
#define MODE_Y  2

template <int MODE>
__global__ __launch_bounds__(256, 2)
void gemm_kernel(const float* __restrict__ u, float* __restrict__ Yout) {
    constexpr int BK = 8;
    constexpr int NK = 512 / BK;   // 64 k-tiles

    __shared__ float As[2][BK][128];
    __shared__ float Ws[2][BK][128];

    const float* __restrict__ W =
        (MODE == MODE_X) ? g_Bq : (MODE == MODE_DU ? g_Dq : g_Cq);

    const int tid = threadIdx.x;
    const int m0  = blockIdx.x * 128;
    const int n0  = blockIdx.y * 128;
    const int b   = m0 >> 9;       // tiles never straddle batches (128 | 512)
    const int t0  = m0 & 511;

    // ---- loader indices ----
    const int wn = tid >> 1;             // 0..127
    const int wk = (tid & 1) * 4;        // 0 or 4
    const float* wptr = W + (n0 + wn) * 512 + wk;

    const float* aptr;
    int a_kl = 0, a_tl = 0;
    if (MODE == MODE_Y) {
        aptr = g_S + (m0 + wn) * 512 + wk;             // row-major, transpose on STS
    } else {
        a_kl = tid >> 5;                               // 0..7
        a_tl = (tid & 31) << 2;                        // 0..124
        aptr = u + b * (DIN * LT) + a_kl * LT + t0 + a_tl;  // t-contiguous float4
    }

    // ---- compute thread map: lane-fast dim matches output-contiguous dim ----
    int tm, tn;
    if (MODE == MODE_X) { tn = tid & 15; tm = tid >> 4; }
    else                { tm = tid & 15; tn = tid >> 4; }

    float acc[8][8];
#pragma unroll
    for (int i = 0; i < 8; i++)
#pragma unroll
        for (int j = 0; j < 8; j++) acc[i][j] = 0.0f;

    // ---- prologue: tile 0 -> smem buf 0 ----
    {
        float4 w4 = *(const float4*)(wptr);
        Ws[0][wk+0][wn] = w4.x; Ws[0][wk+1][wn] = w4.y;
        Ws[0][wk+2][wn] = w4.z; Ws[0][wk+3][wn] = w4.w;
        if (MODE == MODE_Y) {
            float4 a4 = *(const float4*)(aptr);
            As[0][wk+0][wn] = a4.x; As[0][wk+1][wn] = a4.y;
            As[0][wk+2][wn] = a4.z; As[0][wk+3][wn] = a4.w;
        } else {
            *(float4*)&As[0][a_kl][a_tl] = *(const float4*)(aptr);
        }
    }
    __syncthreads();

    // ---- main loop: double-buffered with register staging ----
    for (int kt = 0; kt < NK; kt++) {
        const int buf = kt & 1;
        const bool more = (kt + 1 < NK);
        float4 na, nw;
        if (more) {
            const int k0 = (kt + 1) * BK;
            nw = *(const float4*)(wptr + k0);
            if (MODE == MODE_Y) na = *(const float4*)(aptr + k0);
            else                na = *(const float4*)(aptr + k0 * LT);
        }

#pragma unroll
        for (int kk = 0; kk < BK; kk++) {
            float ra[8], rw[8];
#pragma unroll
            for (int i = 0; i < 8; i++) ra[i] = As[buf][kk][tm + 16*i];
#pragma unroll
            for (int j = 0; j < 8; j++) rw[j] = Ws[buf][kk][tn + 16*j];
#pragma unroll
            for (int i = 0; i < 8; i++)
#pragma unroll
                for (int j = 0; j < 8; j++)
                    acc[i][j] = fmaf(ra[i], rw[j], acc[i][j]);
        }

        if (more) {
            const int nb = buf ^ 1;
            Ws[nb][wk+0][wn] = nw.x; Ws[nb][wk+1][wn] = nw.y;
            Ws[nb][wk+2][wn] = nw.z; Ws[nb][wk+3][wn] = nw.w;
            if (MODE == MODE_Y) {
                As[nb][wk+0][wn] = na.x; As[nb][wk+1][wn] = na.y;
                As[nb][wk+2][wn] = na.z; As[nb][wk+3][wn] = na.w;
            } else {
                *(float4*)&As[nb][a_kl][a_tl] = na;
            }
        }
        __syncthreads();
    }

    // ---- epilogue ----
    if (MODE == MODE_X) {
#pragma unroll
        for (int i = 0; i < 8; i++) {
            const int m = m0 + tm + 16*i;
#pragma unroll
            for (int j = 0; j < 8; j++) {
                const int n = n0 + tn + 16*j;
                g_X[m * 512 + n] = acc[i][j];
            }
        }
    } else if (MODE == MODE_DU) {
#pragma unroll
        for (int i = 0; i < 8; i++) {
            const int t = t0 + tm + 16*i;
#pragma unroll
            for (int j = 0; j < 8; j++) {
                const int o = n0 + tn + 16*j;
                g_DU[(b * 512 + o) * 512 + t] = acc[i][j];
            }
        }
    } else {  // MODE_Y
#pragma unroll
        for (int i = 0; i < 8; i++) {
            const int t = t0 + tm + 16*i;
#pragma unroll
            for (int j = 0; j < 8; j++) {
                const int o = n0 + tn + 16*j;
                const int idx = (b * 512 + o) * 512 + t;
                // association matches ref: (S@C^T) + (u@D^T), then quantize
                Yout[idx] = q8(acc[i][j] + g_DU[idx]);
            }
        }
    }
}

// ---------------- sequential scan over t (one thread per (b,n) strand) -------
__global__ void scan_kernel() {
    const int id = blockIdx.x * blockDim.x + threadIdx.x;   // 0..16383
    const int n  = id & 511;
    const int bb = id >> 9;
    const float a = g_Aq[n];
    const float* __restrict__ xp = g_X + (size_t)(bb * 512) * 512 + n;
    float*       __restrict__ sp = g_S + (size_t)(bb * 512) * 512 + n;

    float s = 0.0f;
    float buf[8];
#pragma unroll
    for (int k = 0; k < 8; k++) buf[k] = xp[k * 512];

    for (int blk = 0; blk < 64; blk++) {
        float nbuf[8];
        if (blk < 63) {
#pragma unroll
            for (int k = 0; k < 8; k++) nbuf[k] = xp[((blk + 1) * 8 + k) * 512];
        } else {
#pragma unroll
            for (int k = 0; k < 8; k++) nbuf[k] = 0.0f;
        }
#pragma unroll
        for (int k = 0; k < 8; k++) {
            // unfused mul+add to match reference's (state*A + x) rounding
            s = q8(__fadd_rn(__fmul_rn(s, a), buf[k]));
            sp[(blk * 8 + k) * 512] = s;
        }
#pragma unroll
        for (int k = 0; k < 8; k++) buf[k] = nbuf[k];
    }
}

// ---------------- launch ------------------------------------------------------
extern "C" void kernel_launch(void* const* d_in, const int* in_sizes, int n_in,
                              void* d_out, int out_size) {
    const float* u = (const float*)d_in[0];   // (32, 512, 512)  u[b,d,t]
    const float* A = (const float*)d_in[1];   // (512,)
    const float* B = (const float*)d_in[2];   // (512, 512)
    const float* C = (const float*)d_in[3];   // (512, 512)
    const float* D = (const float*)d_in[4];   // (512, 512)
    float* Y = (float*)d_out;                 // (32, 512, 512)  Y[b,o,t]

    quant_weights<<<(NS * DIN + 255) / 256, 256>>>(A, B, C, D);

    dim3 g(MTOT / 128, 512 / 128);            // (128, 4)
    gemm_kernel<MODE_X ><<<g, 256>>>(u, nullptr);  // X  = u @ Bq^T  -> [b,t,n]
    gemm_kernel<MODE_DU><<<g, 256>>>(u, nullptr);  // DU = u @ Dq^T  -> [b,o,t]

    scan_kernel<<<(BZ * NS) / 256, 256>>>();       // 64 blocks x 256 = 16384 strands

    gemm_kernel<MODE_Y ><<<g, 256>>>(u, Y);        // Y = q8(S @ Cq^T + DU) -> [b,o,t]
}

// round 8
// speedup vs baseline: 1.7163x; 1.7163x over previous
#include <cuda_runtime.h>
#include <cuda_bf16.h>
#include <math.h>
#include <stdint.h>

// Problem dims (fixed by the dataset)
#define LT   512   // sequence length L
#define DIN  512
#define NS   512   // state dim N
#define DOUT 512
#define BZ   32
#define MTOT (BZ*LT)

// ---------------- scratch (device globals; no allocation allowed) ------------
__device__ float          g_Bq [NS*DIN];      // fp32 (exact X GEMM)
__device__ __nv_bfloat16  g_Dqb[DOUT*DIN];    // bf16 (exact: 4-bit mantissa values)
__device__ __nv_bfloat16  g_Cqb[DOUT*NS];     // bf16 (exact)
__device__ float          g_Aq [NS];
__device__ float          g_X  [BZ*LT*NS];    // X[b,t,n] fp32 (bit-exact, feeds scan)
__device__ float          g_DU [BZ*DOUT*LT];  // DU[b,o,t] fp32
__device__ __nv_bfloat16  g_Sb [BZ*LT*NS];    // S[b,t,n] bf16 (exact: q8 values)
__device__ __nv_bfloat16  g_uhiT[BZ*LT*DIN];  // u^T hi [b,t,d] bf16
__device__ __nv_bfloat16  g_uloT[BZ*LT*DIN];  // u^T lo [b,t,d] bf16

// ---------------- quantizer: matches reference to_float8(4,3) ----------------
__device__ __forceinline__ float q8(float x) {
    float xa = fabsf(x);
    float z  = xa + 1e-8f;                       // always normal (>= 1e-8)
    int   e  = (__float_as_int(z) >> 23) - 127;  // floor(log2 z), exact
    e = max(-7, min(7, e));
    float p    = __int_as_float((e + 127) << 23);
    float pinv = __int_as_float((127 - e) << 23);
    float mant = rintf(fmaf(xa, pinv, -1.0f) * 8.0f) * 0.125f;  // RNE = jnp.round
    float r = (1.0f + mant) * p;
    return copysignf(r, x);
}

// ---------------- weight quantization ----------------------------------------
__global__ void quant_weights(const float* __restrict__ A, const float* __restrict__ B,
                              const float* __restrict__ C, const float* __restrict__ D) {
    int i = blockIdx.x * blockDim.x + threadIdx.x;
    if (i < NS*DIN) {
        g_Bq [i] = q8(B[i]);
        g_Dqb[i] = __float2bfloat16(q8(D[i]));   // exact: 4-bit mantissa
        g_Cqb[i] = __float2bfloat16(q8(C[i]));   // exact
    }
    if (i < NS) g_Aq[i] = q8(A[i]);
}

// ---------------- u -> transposed hi/lo bf16 split ----------------------------
// reads u[b,d,t] fp32, writes u^T[b,t,d] as hi=bf16(u), lo=bf16(u-hi).
// (hi+lo reconstructs u to relative 2^-18.)
__global__ void convert_u(const float* __restrict__ u) {
    __shared__ float tile[32][33];
    const int b  = blockIdx.z;
    const int d0 = blockIdx.y * 32;
    const int t0 = blockIdx.x * 32;
    const int tx = threadIdx.x & 31;
    const int ty = threadIdx.x >> 5;   // 0..7
    const size_t ub = (size_t)b * (DIN * LT);
#pragma unroll
    for (int p = 0; p < 4; p++)
        tile[ty + 8*p][tx] = u[ub + (size_t)(d0 + ty + 8*p) * LT + t0 + tx];
    __syncthreads();
#pragma unroll
    for (int p = 0; p < 4; p++) {
        float v = tile[tx][ty + 8*p];                 // u[d0+tx][t0+ty+8p]
        __nv_bfloat16 hi = __float2bfloat16(v);
        float r = v - __bfloat162float(hi);           // exact (Sterbenz)
        __nv_bfloat16 lo = __float2bfloat16(r);
        size_t idx = ub + (size_t)(t0 + ty + 8*p) * DIN + d0 + tx;
        g_uhiT[idx] = hi;
        g_uloT[idx] = lo;
    }
}

// ---------------- exact fp32 GEMM for X (unchanged from bit-exact baseline) ---
// X[m,n] = sum_d u[b,d,t]*Bq[n,d], m=b*512+t, ascending-k fma chain.
__global__ __launch_bounds__(256, 2)
void gemm_x(const float* __restrict__ u) {
    constexpr int BK = 8;
    constexpr int NK = 512 / BK;

    __shared__ float As[2][BK][128];
    __shared__ float Ws[2][BK][128];

    const int tid = threadIdx.x;
    const int m0  = blockIdx.x * 128;
    const int n0  = blockIdx.y * 128;
    const int b   = m0 >> 9;
    const int t0  = m0 & 511;

    const int wn = tid >> 1;
    const int wk = (tid & 1) * 4;
    const float* wptr = g_Bq + (n0 + wn) * 512 + wk;

    const int a_kl = tid >> 5;
    const int a_tl = (tid & 31) << 2;
    const float* aptr = u + b * (DIN * LT) + a_kl * LT + t0 + a_tl;

    const int tn = tid & 15, tm = tid >> 4;

    float acc[8][8];
#pragma unroll
    for (int i = 0; i < 8; i++)
#pragma unroll
        for (int j = 0; j < 8; j++) acc[i][j] = 0.0f;

    {
        float4 w4 = *(const float4*)(wptr);
        Ws[0][wk+0][wn] = w4.x; Ws[0][wk+1][wn] = w4.y;
        Ws[0][wk+2][wn] = w4.z; Ws[0][wk+3][wn] = w4.w;
        *(float4*)&As[0][a_kl][a_tl] = *(const float4*)(aptr);
    }
    __syncthreads();

    for (int kt = 0; kt < NK; kt++) {
        const int buf = kt & 1;
        const bool more = (kt + 1 < NK);
        float4 na, nw;
        if (more) {
            const int k0 = (kt + 1) * BK;
            nw = *(const float4*)(wptr + k0);
            na = *(const float4*)(aptr + k0 * LT);
        }
#pragma unroll
        for (int kk = 0; kk < BK; kk++) {
            float ra[8], rw[8];
#pragma unroll
            for (int i = 0; i < 8; i++) ra[i] = As[buf][kk][tm + 16*i];
#pragma unroll
            for (int j = 0; j < 8; j++) rw[j] = Ws[buf][kk][tn + 16*j];
#pragma unroll
            for (int i = 0; i < 8; i++)
#pragma unroll
                for (int j = 0; j < 8; j++)
                    acc[i][j] = fmaf(ra[i], rw[j], acc[i][j]);
        }
        if (more) {
            const int nb = buf ^ 1;
            Ws[nb][wk+0][wn] = nw.x; Ws[nb][wk+1][wn] = nw.y;
            Ws[nb][wk+2][wn] = nw.z; Ws[nb][wk+3][wn] = nw.w;
            *(float4*)&As[nb][a_kl][a_tl] = na;
        }
        __syncthreads();
    }

#pragma unroll
    for (int i = 0; i < 8; i++) {
        const int m = m0 + tm + 16*i;
#pragma unroll
        for (int j = 0; j < 8; j++)
            g_X[m * 512 + n0 + tn + 16*j] = acc[i][j];
    }
}

// ---------------- sequential scan (writes S as bf16 — exact) ------------------
__global__ void scan_kernel() {
    const int id = blockIdx.x * blockDim.x + threadIdx.x;
    const int n  = id & 511;
    const int bb = id >> 9;
    const float a = g_Aq[n];
    const float* __restrict__ xp = g_X + (size_t)(bb * 512) * 512 + n;
    __nv_bfloat16* __restrict__ sp = g_Sb + (size_t)(bb * 512) * 512 + n;

    float s = 0.0f;
    float buf[8];
#pragma unroll
    for (int k = 0; k < 8; k++) buf[k] = xp[k * 512];

    for (int blk = 0; blk < 64; blk++) {
        float nbuf[8];
        if (blk < 63) {
#pragma unroll
            for (int k = 0; k < 8; k++) nbuf[k] = xp[((blk + 1) * 8 + k) * 512];
        } else {
#pragma unroll
            for (int k = 0; k < 8; k++) nbuf[k] = 0.0f;
        }
#pragma unroll
        for (int k = 0; k < 8; k++) {
            s = q8(__fadd_rn(__fmul_rn(s, a), buf[k]));   // unfused, matches ref
            sp[(blk * 8 + k) * 512] = __float2bfloat16(s); // exact
        }
#pragma unroll
        for (int k = 0; k < 8; k++) buf[k] = nbuf[k];
    }
}

// ---------------- bf16 tensor-core GEMM (mma.sync m16n8k16) -------------------
// Computes out[b][o][t] = sum_k A[o][k] * Bmat[b][t][k]
//   IS_Y=false (DU): A = Dqb, Bmat = uhiT then uloT (NC=32 chunks, split-k over the two)
//   IS_Y=true  (Y) : A = Cqb, Bmat = Sb (NC=16), epilogue Y = q8(acc + DU)
// CTA: 128(o) x 128(t), 8 warps as 2x4, warp tile 64x32, BK=32 double-buffered.
__device__ __forceinline__ void mma16816(float c[4], const uint32_t a[4], const uint32_t b[2]) {
    asm volatile(
        "mma.sync.aligned.m16n8k16.row.col.f32.bf16.bf16.f32 "
        "{%0,%1,%2,%3}, {%4,%5,%6,%7}, {%8,%9}, {%0,%1,%2,%3};"
        : "+f"(c[0]), "+f"(c[1]), "+f"(c[2]), "+f"(c[3])
        : "r"(a[0]), "r"(a[1]), "r"(a[2]), "r"(a[3]), "r"(b[0]), "r"(b[1]));
}

template <bool IS_Y>
__global__ __launch_bounds__(256, 2)
void tc_gemm(float* __restrict__ Yout) {
    constexpr int NC   = IS_Y ? 16 : 32;   // 32-wide k-chunks (x2 for hi/lo split)
    constexpr int PITCH = 40;              // bf16 elems per smem row (conflict-free)

    __shared__ __nv_bfloat16 sA[2][128][PITCH];
    __shared__ __nv_bfloat16 sB[2][128][PITCH];

    const int tid  = threadIdx.x;
    const int wid  = tid >> 5, lane = tid & 31;
    const int g    = lane >> 2, tq = lane & 3;
    const int wm   = wid >> 2;             // 0..1  (o dim, 64 each)
    const int wn   = wid & 3;              // 0..3  (t dim, 32 each)
    const int t0   = blockIdx.x * 128;
    const int o0   = blockIdx.y * 128;
    const int b    = blockIdx.z;

    const __nv_bfloat16* __restrict__ Ab  = IS_Y ? g_Cqb : g_Dqb;
    const __nv_bfloat16* __restrict__ Bhi = IS_Y ? g_Sb  : g_uhiT;
    const __nv_bfloat16* __restrict__ Blo = g_uloT;

    // loaders: 256 thr, 2 per row; each thread 16 bf16 (two uint4)
    const int lrow = tid >> 1;
    const int lcol = (tid & 1) << 4;
    const __nv_bfloat16* Ap = Ab + (size_t)(o0 + lrow) * 512 + lcol;
    const size_t boff = ((size_t)b << 18) + (size_t)(t0 + lrow) * 512 + lcol;

    uint4 ra0, ra1, rb0, rb1;
    auto ldg = [&](int c) {
        const uint4* pa = (const uint4*)(Ap + (c & 15) * 32);
        ra0 = pa[0]; ra1 = pa[1];
        const __nv_bfloat16* src = (!IS_Y && c >= 16) ? Blo : Bhi;
        const uint4* pb = (const uint4*)(src + boff + (size_t)(c & 15) * 32);
        rb0 = pb[0]; rb1 = pb[1];
    };
    auto sts = [&](int bi) {
        *(uint4*)&sA[bi][lrow][lcol]     = ra0;
        *(uint4*)&sA[bi][lrow][lcol + 8] = ra1;
        *(uint4*)&sB[bi][lrow][lcol]     = rb0;
        *(uint4*)&sB[bi][lrow][lcol + 8] = rb1;
    };

    float acc[4][4][4];
#pragma unroll
    for (int i = 0; i < 4; i++)
#pragma unroll
        for (int j = 0; j < 4; j++)
#pragma unroll
            for (int r = 0; r < 4; r++) acc[i][j][r] = 0.0f;

    ldg(0); sts(0); __syncthreads();

    for (int c = 0; c < NC; c++) {
        const int bi = c & 1;
        const bool more = (c + 1 < NC);
        if (more) ldg(c + 1);

#pragma unroll
        for (int s = 0; s < 2; s++) {               // two k16 steps per chunk
            const int ka = s * 16 + 2 * tq;
            uint32_t af[4][4];
#pragma unroll
            for (int i = 0; i < 4; i++) {
                const int ar = wm * 64 + i * 16 + g;
                af[i][0] = *(const uint32_t*)&sA[bi][ar    ][ka];
                af[i][1] = *(const uint32_t*)&sA[bi][ar + 8][ka];
                af[i][2] = *(const uint32_t*)&sA[bi][ar    ][ka + 8];
                af[i][3] = *(const uint32_t*)&sA[bi][ar + 8][ka + 8];
            }
            uint32_t bfr[4][2];
#pragma unroll
            for (int j = 0; j < 4; j++) {
                const int br = wn * 32 + j * 8 + g;
                bfr[j][0] = *(const uint32_t*)&sB[bi][br][ka];
                bfr[j][1] = *(const uint32_t*)&sB[bi][br][ka + 8];
            }
#pragma unroll
            for (int i = 0; i < 4; i++)
#pragma unroll
                for (int j = 0; j < 4; j++)
                    mma16816(acc[i][j], af[i], bfr[j]);
        }

        if (more) sts(bi ^ 1);
        __syncthreads();
    }

    // epilogue: c0,c1 at (row g, col 2tq,+1); c2,c3 at (row g+8)
#pragma unroll
    for (int i = 0; i < 4; i++) {
#pragma unroll
        for (int j = 0; j < 4; j++) {
            const int o = o0 + wm * 64 + i * 16 + g;
            const int t = t0 + wn * 32 + j * 8 + 2 * tq;
            const size_t rb = ((size_t)(b * 512 + o)) * 512 + t;
            if (!IS_Y) {
                *(float2*)&g_DU[rb]            = make_float2(acc[i][j][0], acc[i][j][1]);
                *(float2*)&g_DU[rb + 8 * 512]  = make_float2(acc[i][j][2], acc[i][j][3]);
            } else {
                float2 d0 = *(const float2*)&g_DU[rb];
                float2 d1 = *(const float2*)&g_DU[rb + 8 * 512];
                *(float2*)&Yout[rb] =
                    make_float2(q8(acc[i][j][0] + d0.x), q8(acc[i][j][1] + d0.y));
                *(float2*)&Yout[rb + 8 * 512] =
                    make_float2(q8(acc[i][j][2] + d1.x), q8(acc[i][j][3] + d1.y));
            }
        }
    }
}

// ---------------- launch ------------------------------------------------------
extern "C" void kernel_launch(void* const* d_in, const int* in_sizes, int n_in,
                              void* d_out, int out_size) {
    const float* u = (const float*)d_in[0];   // (32, 512, 512)  u[b,d,t]
    const float* A = (const float*)d_in[1];
    const float* B = (const float*)d_in[2];
    const float* C = (const float*)d_in[3];
    const float* D = (const float*)d_in[4];
    float* Y = (float*)d_out;                 // (32, 512, 512)  Y[b,o,t]

    quant_weights<<<(NS * DIN + 255) / 256, 256>>>(A, B, C, D);
    convert_u<<<dim3(16, 16, BZ), 256>>>(u);

    gemm_x<<<dim3(MTOT / 128, 4), 256>>>(u);          // X (exact fp32) -> [b,t,n]
    tc_gemm<false><<<dim3(4, 4, BZ), 256>>>(nullptr); // DU = u @ Dq^T (TC, hi+lo)
    scan_kernel<<<(BZ * NS) / 256, 256>>>();          // S (bf16-exact) from X
    tc_gemm<true><<<dim3(4, 4, BZ), 256>>>(Y);        // Y = q8(S @ Cq^T + DU) (TC)
}

// round 9
// speedup vs baseline: 2.0152x; 1.1741x over previous
#include <cuda_runtime.h>
#include <cuda_bf16.h>
#include <math.h>
#include <stdint.h>

// Problem dims (fixed by the dataset)
#define LT   512
#define DIN  512
#define NS   512
#define DOUT 512
#define BZ   32
#define MTOT (BZ*LT)

// ---------------- scratch (device globals; no allocation allowed) ------------
__device__ float          g_Bq [NS*DIN];
__device__ __nv_bfloat16  g_Dqb[DOUT*DIN];
__device__ __nv_bfloat16  g_Cqb[DOUT*NS];
__device__ float          g_Aq [NS];
__device__ float          g_X  [BZ*LT*NS];    // X[b,t,n] fp32 (bit-exact)
__device__ float          g_DU [BZ*DOUT*LT];  // DU[b,o,t]
__device__ __nv_bfloat16  g_Sb [BZ*LT*NS];    // S[b,t,n] bf16 (exact)
__device__ __nv_bfloat16  g_uhiT[BZ*LT*DIN];  // u^T hi [b,t,d]
__device__ __nv_bfloat16  g_uloT[BZ*LT*DIN];  // u^T lo [b,t,d]

// ---------------- quantizer (unchanged — proven bit-exact in round 7) --------
__device__ __forceinline__ float q8(float x) {
    float xa = fabsf(x);
    float z  = xa + 1e-8f;
    int   e  = (__float_as_int(z) >> 23) - 127;
    e = max(-7, min(7, e));
    float p    = __int_as_float((e + 127) << 23);
    float pinv = __int_as_float((127 - e) << 23);
    float mant = rintf(fmaf(xa, pinv, -1.0f) * 8.0f) * 0.125f;
    float r = (1.0f + mant) * p;
    return copysignf(r, x);
}

// ---------------- weight quantization ----------------------------------------
__global__ void quant_weights(const float* __restrict__ A, const float* __restrict__ B,
                              const float* __restrict__ C, const float* __restrict__ D) {
    int i = blockIdx.x * blockDim.x + threadIdx.x;
    if (i < NS*DIN) {
        g_Bq [i] = q8(B[i]);
        g_Dqb[i] = __float2bfloat16(q8(D[i]));
        g_Cqb[i] = __float2bfloat16(q8(C[i]));
    }
    if (i < NS) g_Aq[i] = q8(A[i]);
}

// ---------------- shared-memory unions ----------------------------------------
struct XSmem  { float As[2][8][128]; float Ws[2][8][128]; };                  // 16 KB
struct CSmem  { float tile[32][33]; };                                        // 4.2 KB
struct TcSmem { __nv_bfloat16 A[2][128][40]; __nv_bfloat16 B[2][128][40]; };  // 40 KB
#define TC_BUF_BYTES (128*40*2)   // 10240 bytes per buffer per operand

__device__ __forceinline__ uint32_t smem_u32p(const void* p) {
    return (uint32_t)__cvta_generic_to_shared(p);
}
__device__ __forceinline__ void ldsm4(uint32_t r[4], uint32_t addr) {
    asm volatile("ldmatrix.sync.aligned.m8n8.x4.shared.b16 {%0,%1,%2,%3}, [%4];"
                 : "=r"(r[0]), "=r"(r[1]), "=r"(r[2]), "=r"(r[3]) : "r"(addr));
}
__device__ __forceinline__ void mma16816(float c[4], const uint32_t a[4], uint32_t b0, uint32_t b1) {
    asm volatile(
        "mma.sync.aligned.m16n8k16.row.col.f32.bf16.bf16.f32 "
        "{%0,%1,%2,%3}, {%4,%5,%6,%7}, {%8,%9}, {%0,%1,%2,%3};"
        : "+f"(c[0]), "+f"(c[1]), "+f"(c[2]), "+f"(c[3])
        : "r"(a[0]), "r"(a[1]), "r"(a[2]), "r"(a[3]), "r"(b0), "r"(b1));
}

// ---------------- gemm_x body (exact fp32, unchanged arithmetic) --------------
__device__ void gemm_x_body(const float* __restrict__ u, int bx, int by, XSmem& S) {
    constexpr int BK = 8;
    constexpr int NK = 512 / BK;

    const int tid = threadIdx.x;
    const int m0  = bx * 128;
    const int n0  = by * 128;
    const int b   = m0 >> 9;
    const int t0  = m0 & 511;

    const int wn = tid >> 1;
    const int wk = (tid & 1) * 4;
    const float* wptr = g_Bq + (n0 + wn) * 512 + wk;

    const int a_kl = tid >> 5;
    const int a_tl = (tid & 31) << 2;
    const float* aptr = u + b * (DIN * LT) + a_kl * LT + t0 + a_tl;

    const int tn = tid & 15, tm = tid >> 4;

    float acc[8][8];
#pragma unroll
    for (int i = 0; i < 8; i++)
#pragma unroll
        for (int j = 0; j < 8; j++) acc[i][j] = 0.0f;

    {
        float4 w4 = *(const float4*)(wptr);
        S.Ws[0][wk+0][wn] = w4.x; S.Ws[0][wk+1][wn] = w4.y;
        S.Ws[0][wk+2][wn] = w4.z; S.Ws[0][wk+3][wn] = w4.w;
        *(float4*)&S.As[0][a_kl][a_tl] = *(const float4*)(aptr);
    }
    __syncthreads();

    for (int kt = 0; kt < NK; kt++) {
        const int buf = kt & 1;
        const bool more = (kt + 1 < NK);
        float4 na, nw;
        if (more) {
            const int k0 = (kt + 1) * BK;
            nw = *(const float4*)(wptr + k0);
            na = *(const float4*)(aptr + k0 * LT);
        }
#pragma unroll
        for (int kk = 0; kk < BK; kk++) {
            float ra[8], rw[8];
#pragma unroll
            for (int i = 0; i < 8; i++) ra[i] = S.As[buf][kk][tm + 16*i];
#pragma unroll
            for (int j = 0; j < 8; j++) rw[j] = S.Ws[buf][kk][tn + 16*j];
#pragma unroll
            for (int i = 0; i < 8; i++)
#pragma unroll
                for (int j = 0; j < 8; j++)
                    acc[i][j] = fmaf(ra[i], rw[j], acc[i][j]);
        }
        if (more) {
            const int nb = buf ^ 1;
            S.Ws[nb][wk+0][wn] = nw.x; S.Ws[nb][wk+1][wn] = nw.y;
            S.Ws[nb][wk+2][wn] = nw.z; S.Ws[nb][wk+3][wn] = nw.w;
            *(float4*)&S.As[nb][a_kl][a_tl] = na;
        }
        __syncthreads();
    }

#pragma unroll
    for (int i = 0; i < 8; i++) {
        const int m = m0 + tm + 16*i;
#pragma unroll
        for (int j = 0; j < 8; j++)
            g_X[m * 512 + n0 + tn + 16*j] = acc[i][j];
    }
}

// ---------------- convert body: one 32x32 transpose tile -----------------------
__device__ void convert_body(const float* __restrict__ u, int gid, CSmem& S) {
    const int x = gid & 15, y = (gid >> 4) & 15, z = gid >> 8;
    const int d0 = y * 32, t0 = x * 32;
    const int tx = threadIdx.x & 31;
    const int ty = threadIdx.x >> 5;
    const size_t ub = (size_t)z * (DIN * LT);
#pragma unroll
    for (int p = 0; p < 4; p++)
        S.tile[ty + 8*p][tx] = u[ub + (size_t)(d0 + ty + 8*p) * LT + t0 + tx];
    __syncthreads();
#pragma unroll
    for (int p = 0; p < 4; p++) {
        float v = S.tile[tx][ty + 8*p];
        __nv_bfloat16 hi = __float2bfloat16(v);
        float r = v - __bfloat162float(hi);
        __nv_bfloat16 lo = __float2bfloat16(r);
        size_t idx = ub + (size_t)(t0 + ty + 8*p) * DIN + d0 + tx;
        g_uhiT[idx] = hi;
        g_uloT[idx] = lo;
    }
    __syncthreads();
}

// ---------------- fused1: gemm_x (even blocks) + convert (odd blocks) ---------
__global__ __launch_bounds__(256, 2)
void fused1(const float* __restrict__ u) {
    __shared__ __align__(16) char sm[sizeof(XSmem)];
    const int role = blockIdx.x & 1;
    const int id   = blockIdx.x >> 1;
    if (role == 0) {
        gemm_x_body(u, id & 127, id >> 7, *reinterpret_cast<XSmem*>(sm));
    } else {
        CSmem& S = *reinterpret_cast<CSmem*>(sm);
        for (int l = 0; l < 16; l++)
            convert_body(u, id * 16 + l, S);
    }
}

// ---------------- tc body: bf16 mma with ldmatrix fragment loads ---------------
// out[b][o][t] = sum_k A[o][k] * Bmat[b][t][k]
//   IS_Y=false: A=Dqb, B=uhiT (chunks 0..15) then uloT (16..31)  -> g_DU
//   IS_Y=true : A=Cqb, B=Sb (chunks 0..15), epilogue Y=q8(acc+DU)
template <bool IS_Y>
__device__ void tc_body(float* __restrict__ Yout, int bxt, int byo, int b, TcSmem& S) {
    constexpr int NC = IS_Y ? 16 : 32;

    const int tid  = threadIdx.x;
    const int wid  = tid >> 5, lane = tid & 31;
    const int g    = lane >> 2, tq = lane & 3;
    const int wm   = wid >> 2;
    const int wn   = wid & 3;
    const int t0   = bxt * 128;
    const int o0   = byo * 128;

    const __nv_bfloat16* __restrict__ Ab  = IS_Y ? g_Cqb : g_Dqb;
    const __nv_bfloat16* __restrict__ Bhi = IS_Y ? g_Sb  : g_uhiT;
    const __nv_bfloat16* __restrict__ Blo = g_uloT;

    // gmem loaders (identical to round 8)
    const int lrow = tid >> 1;
    const int lcol = (tid & 1) << 4;
    const __nv_bfloat16* Ap = Ab + (size_t)(o0 + lrow) * 512 + lcol;
    const size_t boff = ((size_t)b << 18) + (size_t)(t0 + lrow) * 512 + lcol;

    uint4 ra0, ra1, rb0, rb1;
    auto ldg = [&](int c) {
        const uint4* pa = (const uint4*)(Ap + (c & 15) * 32);
        ra0 = pa[0]; ra1 = pa[1];
        const __nv_bfloat16* src = (!IS_Y && c >= 16) ? Blo : Bhi;
        const uint4* pb = (const uint4*)(src + boff + (size_t)(c & 15) * 32);
        rb0 = pb[0]; rb1 = pb[1];
    };
    auto sts = [&](int bi) {
        *(uint4*)&S.A[bi][lrow][lcol]     = ra0;
        *(uint4*)&S.A[bi][lrow][lcol + 8] = ra1;
        *(uint4*)&S.B[bi][lrow][lcol]     = rb0;
        *(uint4*)&S.B[bi][lrow][lcol + 8] = rb1;
    };

    // ldmatrix lane addresses (bytes into shared space), buffer 0, s = 0
    //  A tile i: rows wm*64+i*16 + (lane&15), col (lane>>4)*8
    const int arow = wm * 64 + (lane & 15);
    const int acol = (lane >> 4) * 8;
    uint32_t aAddr0 = smem_u32p(&S.A[0][arow][acol]);
    //  B pair jj: rows wn*32+jj*16 + ((lane>>4)&1)*8 + (lane&7), col ((lane>>3)&1)*8
    const int brow = wn * 32 + ((lane >> 4) & 1) * 8 + (lane & 7);
    const int bcol = ((lane >> 3) & 1) * 8;
    uint32_t bAddr0 = smem_u32p(&S.B[0][brow][bcol]);

    float acc[4][4][4];
#pragma unroll
    for (int i = 0; i < 4; i++)
#pragma unroll
        for (int j = 0; j < 4; j++)
#pragma unroll
            for (int r = 0; r < 4; r++) acc[i][j][r] = 0.0f;

    ldg(0); sts(0); __syncthreads();

    for (int c = 0; c < NC; c++) {
        const int bi = c & 1;
        const bool more = (c + 1 < NC);
        if (more) ldg(c + 1);

        const uint32_t aB = aAddr0 + bi * TC_BUF_BYTES;
        const uint32_t bB = bAddr0 + bi * TC_BUF_BYTES;
#pragma unroll
        for (int s = 0; s < 2; s++) {
            const uint32_t so = s * 32;          // 16 bf16 cols = 32 bytes
            uint32_t af[4][4];
#pragma unroll
            for (int i = 0; i < 4; i++)
                ldsm4(af[i], aB + i * (16 * 80) + so);
            uint32_t bq[2][4];
#pragma unroll
            for (int jj = 0; jj < 2; jj++)
                ldsm4(bq[jj], bB + jj * (16 * 80) + so);
#pragma unroll
            for (int i = 0; i < 4; i++)
#pragma unroll
                for (int j = 0; j < 4; j++)
                    mma16816(acc[i][j], af[i], bq[j >> 1][(j & 1) * 2], bq[j >> 1][(j & 1) * 2 + 1]);
        }

        if (more) sts(bi ^ 1);
        __syncthreads();
    }

#pragma unroll
    for (int i = 0; i < 4; i++) {
#pragma unroll
        for (int j = 0; j < 4; j++) {
            const int o = o0 + wm * 64 + i * 16 + g;
            const int t = t0 + wn * 32 + j * 8 + 2 * tq;
            const size_t rb = ((size_t)(b * 512 + o)) * 512 + t;
            if (!IS_Y) {
                *(float2*)&g_DU[rb]           = make_float2(acc[i][j][0], acc[i][j][1]);
                *(float2*)&g_DU[rb + 8 * 512] = make_float2(acc[i][j][2], acc[i][j][3]);
            } else {
                float2 d0 = *(const float2*)&g_DU[rb];
                float2 d1 = *(const float2*)&g_DU[rb + 8 * 512];
                *(float2*)&Yout[rb] =
                    make_float2(q8(acc[i][j][0] + d0.x), q8(acc[i][j][1] + d0.y));
                *(float2*)&Yout[rb + 8 * 512] =
                    make_float2(q8(acc[i][j][2] + d1.x), q8(acc[i][j][3] + d1.y));
            }
        }
    }
}

// ---------------- scan body (unchanged arithmetic) -----------------------------
__device__ void scan_body(int id) {
    const int n  = id & 511;
    const int bb = id >> 9;
    const float a = g_Aq[n];
    const float* __restrict__ xp = g_X + (size_t)(bb * 512) * 512 + n;
    __nv_bfloat16* __restrict__ sp = g_Sb + (size_t)(bb * 512) * 512 + n;

    float s = 0.0f;
    float buf[8];
#pragma unroll
    for (int k = 0; k < 8; k++) buf[k] = xp[k * 512];

    for (int blk = 0; blk < 64; blk++) {
        float nbuf[8];
        if (blk < 63) {
#pragma unroll
            for (int k = 0; k < 8; k++) nbuf[k] = xp[((blk + 1) * 8 + k) * 512];
        } else {
#pragma unroll
            for (int k = 0; k < 8; k++) nbuf[k] = 0.0f;
        }
#pragma unroll
        for (int k = 0; k < 8; k++) {
            s = q8(__fadd_rn(__fmul_rn(s, a), buf[k]));
            sp[(blk * 8 + k) * 512] = __float2bfloat16(s);
        }
#pragma unroll
        for (int k = 0; k < 8; k++) buf[k] = nbuf[k];
    }
}

// ---------------- fused2: scan (blocks 0-63) + tc<DU> (blocks 64-575) ----------
__global__ __launch_bounds__(256, 2)
void fused2() {
    __shared__ __align__(16) char sm[sizeof(TcSmem)];
    if (blockIdx.x < 64) {
        scan_body(blockIdx.x * 256 + threadIdx.x);
    } else {
        const int id = blockIdx.x - 64;          // 0..511 = 4 x 4 x 32
        tc_body<false>(nullptr, id & 3, (id >> 2) & 3, id >> 4,
                       *reinterpret_cast<TcSmem*>(sm));
    }
}

// ---------------- Y kernel ------------------------------------------------------
__global__ __launch_bounds__(256, 2)
void tc_y(float* __restrict__ Y) {
    __shared__ __align__(16) char sm[sizeof(TcSmem)];
    tc_body<true>(Y, blockIdx.x, blockIdx.y, blockIdx.z,
                  *reinterpret_cast<TcSmem*>(sm));
}

// ---------------- launch --------------------------------------------------------
extern "C" void kernel_launch(void* const* d_in, const int* in_sizes, int n_in,
                              void* d_out, int out_size) {
    const float* u = (const float*)d_in[0];   // (32, 512, 512)  u[b,d,t]
    const float* A = (const float*)d_in[1];
    const float* B = (const float*)d_in[2];
    const float* C = (const float*)d_in[3];
    const float* D = (const float*)d_in[4];
    float* Y = (float*)d_out;                 // (32, 512, 512)  Y[b,o,t]

    quant_weights<<<1024, 256>>>(A, B, C, D);
    fused1<<<1024, 256>>>(u);                 // gemm_x (X exact) || u hi/lo transpose
    fused2<<<576, 256>>>();                   // scan (S) || DU tensor GEMM
    tc_y<<<dim3(4, 4, BZ), 256>>>(Y);         // Y = q8(S @ Cq^T + DU)
}

// round 10
// speedup vs baseline: 2.1085x; 1.0463x over previous
#include <cuda_runtime.h>
#include <cuda_bf16.h>
#include <math.h>
#include <stdint.h>

// Problem dims (fixed by the dataset)
#define LT   512
#define DIN  512
#define NS   512
#define DOUT 512
#define BZ   32
#define MTOT (BZ*LT)

// ---------------- scratch (device globals; no allocation allowed) ------------
__device__ float          g_Bq [NS*DIN];
__device__ __nv_bfloat16  g_Dqb[DOUT*DIN];
__device__ __nv_bfloat16  g_Cqb[DOUT*NS];
__device__ float          g_Aq [NS];
__device__ float          g_X  [BZ*LT*NS];    // X[b,t,n] fp32 (bit-exact)
__device__ float          g_DU [BZ*DOUT*LT];  // DU[b,o,t]
__device__ __nv_bfloat16  g_Sb [BZ*LT*NS];    // S[b,t,n] bf16 (exact)
__device__ __nv_bfloat16  g_uhiT[BZ*LT*DIN];  // u^T hi [b,t,d]
__device__ __nv_bfloat16  g_uloT[BZ*LT*DIN];  // u^T lo [b,t,d]

// ---------------- quantizer (proven bit-exact) --------------------------------
__device__ __forceinline__ float q8(float x) {
    float xa = fabsf(x);
    float z  = xa + 1e-8f;
    int   e  = (__float_as_int(z) >> 23) - 127;
    e = max(-7, min(7, e));
    float p    = __int_as_float((e + 127) << 23);
    float pinv = __int_as_float((127 - e) << 23);
    float mant = rintf(fmaf(xa, pinv, -1.0f) * 8.0f) * 0.125f;
    float r = (1.0f + mant) * p;
    return copysignf(r, x);
}

// ---------------- weight quantization ----------------------------------------
__global__ void quant_weights(const float* __restrict__ A, const float* __restrict__ B,
                              const float* __restrict__ C, const float* __restrict__ D) {
    int i = blockIdx.x * blockDim.x + threadIdx.x;
    if (i < NS*DIN) {
        g_Bq [i] = q8(B[i]);
        g_Dqb[i] = __float2bfloat16(q8(D[i]));
        g_Cqb[i] = __float2bfloat16(q8(C[i]));
    }
    if (i < NS) g_Aq[i] = q8(A[i]);
}

// ---------------- shared-memory unions ----------------------------------------
struct XSmem  { float As[2][8][128]; float Ws[2][8][128]; };
struct CSmem  { float tile[32][33]; };
struct TcSmem { __nv_bfloat16 A[2][128][40]; __nv_bfloat16 B[2][128][40]; };
#define TC_BUF_BYTES (128*40*2)

__device__ __forceinline__ uint32_t smem_u32p(const void* p) {
    return (uint32_t)__cvta_generic_to_shared(p);
}
__device__ __forceinline__ void ldsm4(uint32_t r[4], uint32_t addr) {
    asm volatile("ldmatrix.sync.aligned.m8n8.x4.shared.b16 {%0,%1,%2,%3}, [%4];"
                 : "=r"(r[0]), "=r"(r[1]), "=r"(r[2]), "=r"(r[3]) : "r"(addr));
}
__device__ __forceinline__ void mma16816(float c[4], const uint32_t a[4], uint32_t b0, uint32_t b1) {
    asm volatile(
        "mma.sync.aligned.m16n8k16.row.col.f32.bf16.bf16.f32 "
        "{%0,%1,%2,%3}, {%4,%5,%6,%7}, {%8,%9}, {%0,%1,%2,%3};"
        : "+f"(c[0]), "+f"(c[1]), "+f"(c[2]), "+f"(c[3])
        : "r"(a[0]), "r"(a[1]), "r"(a[2]), "r"(a[3]), "r"(b0), "r"(b1));
}

// packed dual-fp32 fma (Blackwell FFMA2). Two independent IEEE-RN fp32 FMAs.
__device__ __forceinline__ void fma2(unsigned long long& c,
                                     unsigned long long a, unsigned long long b) {
    asm("fma.rn.f32x2 %0, %1, %2, %0;" : "+l"(c) : "l"(a), "l"(b));
}
__device__ __forceinline__ unsigned long long dup2(float x) {
    unsigned long long r; uint32_t u = __float_as_uint(x);
    asm("mov.b64 %0, {%1, %1};" : "=l"(r) : "r"(u));
    return r;
}

// ---------------- gemm_x body: exact fp32 via f32x2 ----------------------------
// Same per-element ascending-k fma chain as the bit-exact baseline; lanes of the
// packed op are independent n columns, so X is bit-identical.
__device__ void gemm_x_body(const float* __restrict__ u, int bx, int by, XSmem& S) {
    constexpr int BK = 8;
    constexpr int NK = 512 / BK;

    const int tid = threadIdx.x;
    const int m0  = bx * 128;
    const int n0  = by * 128;
    const int b   = m0 >> 9;
    const int t0  = m0 & 511;

    const int wn = tid >> 1;
    const int wk = (tid & 1) * 4;
    const float* wptr = g_Bq + (n0 + wn) * 512 + wk;

    const int a_kl = tid >> 5;
    const int a_tl = (tid & 31) << 2;
    const float* aptr = u + b * (DIN * LT) + a_kl * LT + t0 + a_tl;

    const int tn = tid & 15, tm = tid >> 4;

    unsigned long long acc2[8][4];   // 8 m-rows x 4 n-pairs (adjacent n)
#pragma unroll
    for (int i = 0; i < 8; i++)
#pragma unroll
        for (int jj = 0; jj < 4; jj++) acc2[i][jj] = 0ULL;

    {
        float4 w4 = *(const float4*)(wptr);
        S.Ws[0][wk+0][wn] = w4.x; S.Ws[0][wk+1][wn] = w4.y;
        S.Ws[0][wk+2][wn] = w4.z; S.Ws[0][wk+3][wn] = w4.w;
        *(float4*)&S.As[0][a_kl][a_tl] = *(const float4*)(aptr);
    }
    __syncthreads();

    for (int kt = 0; kt < NK; kt++) {
        const int buf = kt & 1;
        const bool more = (kt + 1 < NK);
        float4 na, nw;
        if (more) {
            const int k0 = (kt + 1) * BK;
            nw = *(const float4*)(wptr + k0);
            na = *(const float4*)(aptr + k0 * LT);
        }
#pragma unroll
        for (int kk = 0; kk < BK; kk++) {
            unsigned long long rad[8];
#pragma unroll
            for (int i = 0; i < 8; i++)
                rad[i] = dup2(S.As[buf][kk][tm + 16*i]);
            unsigned long long rw2[4];
#pragma unroll
            for (int jj = 0; jj < 4; jj++)
                rw2[jj] = *(const unsigned long long*)&S.Ws[buf][kk][2*tn + 32*jj];
#pragma unroll
            for (int i = 0; i < 8; i++)
#pragma unroll
                for (int jj = 0; jj < 4; jj++)
                    fma2(acc2[i][jj], rad[i], rw2[jj]);
        }
        if (more) {
            const int nb = buf ^ 1;
            S.Ws[nb][wk+0][wn] = nw.x; S.Ws[nb][wk+1][wn] = nw.y;
            S.Ws[nb][wk+2][wn] = nw.z; S.Ws[nb][wk+3][wn] = nw.w;
            *(float4*)&S.As[nb][a_kl][a_tl] = na;
        }
        __syncthreads();
    }

#pragma unroll
    for (int i = 0; i < 8; i++) {
        const int m = m0 + tm + 16*i;
#pragma unroll
        for (int jj = 0; jj < 4; jj++) {
            float2 r;
            asm("mov.b64 {%0, %1}, %2;" : "=f"(r.x), "=f"(r.y) : "l"(acc2[i][jj]));
            *(float2*)&g_X[m * 512 + n0 + 2*tn + 32*jj] = r;
        }
    }
}

// ---------------- convert body: one 32x32 transpose tile -----------------------
__device__ void convert_body(const float* __restrict__ u, int gid, CSmem& S) {
    const int x = gid & 15, y = (gid >> 4) & 15, z = gid >> 8;
    const int d0 = y * 32, t0 = x * 32;
    const int tx = threadIdx.x & 31;
    const int ty = threadIdx.x >> 5;
    const size_t ub = (size_t)z * (DIN * LT);
#pragma unroll
    for (int p = 0; p < 4; p++)
        S.tile[ty + 8*p][tx] = u[ub + (size_t)(d0 + ty + 8*p) * LT + t0 + tx];
    __syncthreads();
#pragma unroll
    for (int p = 0; p < 4; p++) {
        float v = S.tile[tx][ty + 8*p];
        __nv_bfloat16 hi = __float2bfloat16(v);
        float r = v - __bfloat162float(hi);
        __nv_bfloat16 lo = __float2bfloat16(r);
        size_t idx = ub + (size_t)(t0 + ty + 8*p) * DIN + d0 + tx;
        g_uhiT[idx] = hi;
        g_uloT[idx] = lo;
    }
    __syncthreads();
}

// ---------------- fused1: gemm_x (even blocks) + convert (odd blocks) ---------
__global__ __launch_bounds__(256, 2)
void fused1(const float* __restrict__ u) {
    __shared__ __align__(16) char sm[sizeof(XSmem)];
    const int role = blockIdx.x & 1;
    const int id   = blockIdx.x >> 1;
    if (role == 0) {
        gemm_x_body(u, id & 127, id >> 7, *reinterpret_cast<XSmem*>(sm));
    } else {
        CSmem& S = *reinterpret_cast<CSmem*>(sm);
        for (int l = 0; l < 16; l++)
            convert_body(u, id * 16 + l, S);
    }
}

// ---------------- tc body: bf16 mma with ldmatrix fragment loads ---------------
template <bool IS_Y>
__device__ void tc_body(float* __restrict__ Yout, int bxt, int byo, int b, TcSmem& S) {
    constexpr int NC = IS_Y ? 16 : 32;

    const int tid  = threadIdx.x;
    const int wid  = tid >> 5, lane = tid & 31;
    const int g    = lane >> 2, tq = lane & 3;
    const int wm   = wid >> 2;
    const int wn   = wid & 3;
    const int t0   = bxt * 128;
    const int o0   = byo * 128;

    const __nv_bfloat16* __restrict__ Ab  = IS_Y ? g_Cqb : g_Dqb;
    const __nv_bfloat16* __restrict__ Bhi = IS_Y ? g_Sb  : g_uhiT;
    const __nv_bfloat16* __restrict__ Blo = g_uloT;

    const int lrow = tid >> 1;
    const int lcol = (tid & 1) << 4;
    const __nv_bfloat16* Ap = Ab + (size_t)(o0 + lrow) * 512 + lcol;
    const size_t boff = ((size_t)b << 18) + (size_t)(t0 + lrow) * 512 + lcol;

    uint4 ra0, ra1, rb0, rb1;
    auto ldg = [&](int c) {
        const uint4* pa = (const uint4*)(Ap + (c & 15) * 32);
        ra0 = pa[0]; ra1 = pa[1];
        const __nv_bfloat16* src = (!IS_Y && c >= 16) ? Blo : Bhi;
        const uint4* pb = (const uint4*)(src + boff + (size_t)(c & 15) * 32);
        rb0 = pb[0]; rb1 = pb[1];
    };
    auto sts = [&](int bi) {
        *(uint4*)&S.A[bi][lrow][lcol]     = ra0;
        *(uint4*)&S.A[bi][lrow][lcol + 8] = ra1;
        *(uint4*)&S.B[bi][lrow][lcol]     = rb0;
        *(uint4*)&S.B[bi][lrow][lcol + 8] = rb1;
    };

    const int arow = wm * 64 + (lane & 15);
    const int acol = (lane >> 4) * 8;
    uint32_t aAddr0 = smem_u32p(&S.A[0][arow][acol]);
    const int brow = wn * 32 + ((lane >> 4) & 1) * 8 + (lane & 7);
    const int bcol = ((lane >> 3) & 1) * 8;
    uint32_t bAddr0 = smem_u32p(&S.B[0][brow][bcol]);

    float acc[4][4][4];
#pragma unroll
    for (int i = 0; i < 4; i++)
#pragma unroll
        for (int j = 0; j < 4; j++)
#pragma unroll
            for (int r = 0; r < 4; r++) acc[i][j][r] = 0.0f;

    ldg(0); sts(0); __syncthreads();

    for (int c = 0; c < NC; c++) {
        const int bi = c & 1;
        const bool more = (c + 1 < NC);
        if (more) ldg(c + 1);

        const uint32_t aB = aAddr0 + bi * TC_BUF_BYTES;
        const uint32_t bB = bAddr0 + bi * TC_BUF_BYTES;
#pragma unroll
        for (int s = 0; s < 2; s++) {
            const uint32_t so = s * 32;
            uint32_t af[4][4];
#pragma unroll
            for (int i = 0; i < 4; i++)
                ldsm4(af[i], aB + i * (16 * 80) + so);
            uint32_t bq[2][4];
#pragma unroll
            for (int jj = 0; jj < 2; jj++)
                ldsm4(bq[jj], bB + jj * (16 * 80) + so);
#pragma unroll
            for (int i = 0; i < 4; i++)
#pragma unroll
                for (int j = 0; j < 4; j++)
                    mma16816(acc[i][j], af[i], bq[j >> 1][(j & 1) * 2], bq[j >> 1][(j & 1) * 2 + 1]);
        }

        if (more) sts(bi ^ 1);
        __syncthreads();
    }

#pragma unroll
    for (int i = 0; i < 4; i++) {
#pragma unroll
        for (int j = 0; j < 4; j++) {
            const int o = o0 + wm * 64 + i * 16 + g;
            const int t = t0 + wn * 32 + j * 8 + 2 * tq;
            const size_t rb = ((size_t)(b * 512 + o)) * 512 + t;
            if (!IS_Y) {
                *(float2*)&g_DU[rb]           = make_float2(acc[i][j][0], acc[i][j][1]);
                *(float2*)&g_DU[rb + 8 * 512] = make_float2(acc[i][j][2], acc[i][j][3]);
            } else {
                float2 d0 = *(const float2*)&g_DU[rb];
                float2 d1 = *(const float2*)&g_DU[rb + 8 * 512];
                *(float2*)&Yout[rb] =
                    make_float2(q8(acc[i][j][0] + d0.x), q8(acc[i][j][1] + d0.y));
                *(float2*)&Yout[rb + 8 * 512] =
                    make_float2(q8(acc[i][j][2] + d1.x), q8(acc[i][j][3] + d1.y));
            }
        }
    }
}

// ---------------- scan body (unchanged arithmetic) -----------------------------
__device__ void scan_body(int id) {
    const int n  = id & 511;
    const int bb = id >> 9;
    const float a = g_Aq[n];
    const float* __restrict__ xp = g_X + (size_t)(bb * 512) * 512 + n;
    __nv_bfloat16* __restrict__ sp = g_Sb + (size_t)(bb * 512) * 512 + n;

    float s = 0.0f;
    float buf[8];
#pragma unroll
    for (int k = 0; k < 8; k++) buf[k] = xp[k * 512];

    for (int blk = 0; blk < 64; blk++) {
        float nbuf[8];
        if (blk < 63) {
#pragma unroll
            for (int k = 0; k < 8; k++) nbuf[k] = xp[((blk + 1) * 8 + k) * 512];
        } else {
#pragma unroll
            for (int k = 0; k < 8; k++) nbuf[k] = 0.0f;
        }
#pragma unroll
        for (int k = 0; k < 8; k++) {
            s = q8(__fadd_rn(__fmul_rn(s, a), buf[k]));
            sp[(blk * 8 + k) * 512] = __float2bfloat16(s);
        }
#pragma unroll
        for (int k = 0; k < 8; k++) buf[k] = nbuf[k];
    }
}

// ---------------- fused2: scan (blocks 0-63) + tc<DU> (blocks 64-575) ----------
__global__ __launch_bounds__(256, 2)
void fused2() {
    __shared__ __align__(16) char sm[sizeof(TcSmem)];
    if (blockIdx.x < 64) {
        scan_body(blockIdx.x * 256 + threadIdx.x);
    } else {
        const int id = blockIdx.x - 64;
        tc_body<false>(nullptr, id & 3, (id >> 2) & 3, id >> 4,
                       *reinterpret_cast<TcSmem*>(sm));
    }
}

// ---------------- Y kernel ------------------------------------------------------
__global__ __launch_bounds__(256, 2)
void tc_y(float* __restrict__ Y) {
    __shared__ __align__(16) char sm[sizeof(TcSmem)];
    tc_body<true>(Y, blockIdx.x, blockIdx.y, blockIdx.z,
                  *reinterpret_cast<TcSmem*>(sm));
}

// ---------------- launch --------------------------------------------------------
extern "C" void kernel_launch(void* const* d_in, const int* in_sizes, int n_in,
                              void* d_out, int out_size) {
    const float* u = (const float*)d_in[0];   // (32, 512, 512)  u[b,d,t]
    const float* A = (const float*)d_in[1];
    const float* B = (const float*)d_in[2];
    const float* C = (const float*)d_in[3];
    const float* D = (const float*)d_in[4];
    float* Y = (float*)d_out;                 // (32, 512, 512)  Y[b,o,t]

    quant_weights<<<1024, 256>>>(A, B, C, D);
    fused1<<<1024, 256>>>(u);                 // gemm_x (FFMA2, bit-exact X) || u hi/lo transpose
    fused2<<<576, 256>>>();                   // scan (S) || DU tensor GEMM
    tc_y<<<dim3(4, 4, BZ), 256>>>(Y);         // Y = q8(S @ Cq^T + DU)
}